// round 4
// baseline (speedup 1.0000x reference)
#include <cuda_runtime.h>
#include <cuda_fp16.h>
#include <math.h>
#include <cstdint>

#define BSZ 4096
#define ISZ 1024
#define HSZ 2048
#define NTH 512

// ---------------------------------------------------------------------------
// Device scratch (fp16 hi/lo planes)
// ---------------------------------------------------------------------------
__device__ __half g_x_hi[BSZ * ISZ],  g_x_lo[BSZ * ISZ];
__device__ __half g_h_hi[BSZ * HSZ],  g_h_lo[BSZ * HSZ];
__device__ __half g_wgxT_hi[HSZ * ISZ], g_wgxT_lo[HSZ * ISZ];
__device__ __half g_wxhT_hi[HSZ * ISZ], g_wxhT_lo[HSZ * ISZ];
__device__ __half g_wghT_hi[HSZ * HSZ], g_wghT_lo[HSZ * HSZ];
__device__ __half g_whhT_hi[HSZ * HSZ], g_whhT_lo[HSZ * HSZ];
__device__ __half g_linw_hi[ISZ * HSZ], g_linw_lo[ISZ * HSZ];
__device__ __half g_hn_hi[BSZ * HSZ],  g_hn_lo[BSZ * HSZ];

// ---------------------------------------------------------------------------
// PTX helpers (sm_80-era only: must compile for plain sm_103 target)
// ---------------------------------------------------------------------------
__device__ __forceinline__ uint32_t smem_u32(const void* p) {
    uint32_t a;
    asm("{ .reg .u64 t; cvta.to.shared.u64 t, %1; cvt.u32.u64 %0, t; }"
        : "=r"(a) : "l"(p));
    return a;
}

#define CP16(dst, src) \
    asm volatile("cp.async.cg.shared.global [%0], [%1], 16;" :: "r"(dst), "l"(src))
#define CP_COMMIT() asm volatile("cp.async.commit_group;" ::: "memory")
#define CP_WAIT0()  asm volatile("cp.async.wait_group 0;" ::: "memory")
#define CP_WAIT1()  asm volatile("cp.async.wait_group 1;" ::: "memory")

#define LDMATRIX_X4(r0, r1, r2, r3, addr)                                   \
    asm volatile("ldmatrix.sync.aligned.m8n8.x4.shared.b16 {%0,%1,%2,%3}, [%4];" \
                 : "=r"(r0), "=r"(r1), "=r"(r2), "=r"(r3) : "r"(addr))

#define MMA16816(c, a, b0, b1)                                              \
    asm volatile("mma.sync.aligned.m16n8k16.row.col.f32.f16.f16.f32 "       \
                 "{%0,%1,%2,%3}, {%4,%5,%6,%7}, {%8,%9}, {%0,%1,%2,%3};"    \
                 : "+f"((c)[0]), "+f"((c)[1]), "+f"((c)[2]), "+f"((c)[3])   \
                 : "r"((a)[0]), "r"((a)[1]), "r"((a)[2]), "r"((a)[3]),      \
                   "r"(b0), "r"(b1))

// ---------------------------------------------------------------------------
// Prep kernels: fp32 -> fp16 (hi, lo) split, optional transpose
// ---------------------------------------------------------------------------
__device__ __forceinline__ void split16(float v, __half& hi, __half& lo) {
    __half h = __float2half_rn(v);
    hi = h;
    lo = __float2half_rn(v - __half2float(h));
}

__global__ void split_kernel(const float4* __restrict__ src,
                             __half2* __restrict__ hi, __half2* __restrict__ lo,
                             int n4) {
    int i = blockIdx.x * blockDim.x + threadIdx.x;
    if (i < n4) {
        float4 v = src[i];
        __half hx, lx, hy, ly, hz, lz, hw, lw;
        split16(v.x, hx, lx); split16(v.y, hy, ly);
        split16(v.z, hz, lz); split16(v.w, hw, lw);
        hi[2 * i]     = __halves2half2(hx, hy);
        hi[2 * i + 1] = __halves2half2(hz, hw);
        lo[2 * i]     = __halves2half2(lx, ly);
        lo[2 * i + 1] = __halves2half2(lz, lw);
    }
}

// src [K,N] row-major -> dst [N,K] fp16 hi/lo
__global__ void transpose_split(const float* __restrict__ src,
                                __half* __restrict__ dhi, __half* __restrict__ dlo,
                                int K, int N) {
    __shared__ float tile[32][33];
    int nb = blockIdx.x * 32, kb = blockIdx.y * 32;
    int tx = threadIdx.x, ty = threadIdx.y;
#pragma unroll
    for (int r = 0; r < 32; r += 8)
        tile[ty + r][tx] = src[(size_t)(kb + ty + r) * N + nb + tx];
    __syncthreads();
#pragma unroll
    for (int r = 0; r < 32; r += 8) {
        float v = tile[tx][ty + r];
        __half h, l;
        split16(v, h, l);
        size_t o = (size_t)(nb + ty + r) * K + kb + tx;
        dhi[o] = h;
        dlo[o] = l;
    }
}

// ---------------------------------------------------------------------------
// Main GEMM: mma.sync m16n8k16 fp16, 3-term compensated.
// 16 warps (512 thr), warp tile 32x32, term-outer MMA order (RAW distance 8).
//   MODE 0: g_new = tanh(x@w_gx + h@w_gh + b)
//   MODE 1: h_new = g*tanh(x@w_xh + h@w_hh + b) + (1-g)*h  (+ split hn out)
//   MODE 2: o = h_new @ lin_w^T + b
// ---------------------------------------------------------------------------
#define RSTRIDE 40                      // halves per smem row (32 + 8 pad)
#define TILE_BYTES (128 * RSTRIDE * 2)  // 10240
#define STAGE_BYTES (4 * TILE_BYTES)    // Ah, Al, Bh, Bl = 40960
#define NSTAGE 3
#define SMEM_MAIN (NSTAGE * STAGE_BYTES)

template <int MODE>
__global__ __launch_bounds__(NTH, 1) void gemm_f16_kernel(
    const float* __restrict__ bias,
    const float* __restrict__ graw,
    const float* __restrict__ hraw,
    float* __restrict__ out)
{
    extern __shared__ __align__(128) unsigned char dsm[];
    const uint32_t sb = smem_u32(dsm);
    const int tid = threadIdx.x;
    const int wid = tid >> 5, lane = tid & 31;
    const int rowBase = blockIdx.y * 128;
    const int colBase = blockIdx.x * 128;
    const int nchunks = (MODE == 2) ? (HSZ / 32) : ((ISZ + HSZ) / 32);
    const int ldout = (MODE == 2) ? ISZ : HSZ;

    const int wm = (wid >> 2) * 32;   // warp m offset (4 row groups)
    const int wn = (wid & 3) * 32;    // warp n offset (4 col groups)

    float acc[2][4][4];
#pragma unroll
    for (int mi = 0; mi < 2; mi++)
#pragma unroll
        for (int ni = 0; ni < 4; ni++)
#pragma unroll
            for (int q = 0; q < 4; q++) acc[mi][ni][q] = 0.0f;

    // ---- chunk loader: 4 tiles x 128 rows x 64B, cp.async 16B ----
    const int ltile = tid >> 7;       // 0 Ah, 1 Al, 2 Bh, 3 Bl
    const int lu = tid & 127;
    auto load_chunk = [&](int c) {
        const int k0 = c * 32;
        const __half *Ah, *Al, *Bh, *Bl;
        int lda, ldb, kk;
        if (MODE == 2) {
            Ah = g_hn_hi; Al = g_hn_lo; lda = HSZ; kk = k0;
            Bh = g_linw_hi; Bl = g_linw_lo; ldb = HSZ;
        } else if (k0 < ISZ) {
            Ah = g_x_hi; Al = g_x_lo; lda = ISZ; kk = k0;
            Bh = (MODE == 0) ? g_wgxT_hi : g_wxhT_hi;
            Bl = (MODE == 0) ? g_wgxT_lo : g_wxhT_lo; ldb = ISZ;
        } else {
            Ah = g_h_hi; Al = g_h_lo; lda = HSZ; kk = k0 - ISZ;
            Bh = (MODE == 0) ? g_wghT_hi : g_whhT_hi;
            Bl = (MODE == 0) ? g_wghT_lo : g_whhT_lo; ldb = HSZ;
        }
        const uint32_t base = sb + (c % NSTAGE) * STAGE_BYTES + ltile * TILE_BYTES;
        const __half* src;
        int ld, rb;
        if (ltile == 0)      { src = Ah; ld = lda; rb = rowBase; }
        else if (ltile == 1) { src = Al; ld = lda; rb = rowBase; }
        else if (ltile == 2) { src = Bh; ld = ldb; rb = colBase; }
        else                 { src = Bl; ld = ldb; rb = colBase; }
#pragma unroll
        for (int i = 0; i < 4; i++) {
            const int id = lu * 4 + i;
            const int row = id >> 2, kc = id & 3;
            CP16(base + row * (RSTRIDE * 2) + kc * 16,
                 src + (size_t)(rb + row) * ld + kk + kc * 8);
        }
        CP_COMMIT();
    };

    load_chunk(0);
    load_chunk(1);

    for (int c = 0; c < nchunks; c++) {
        if (c == nchunks - 1) { CP_WAIT0(); } else { CP_WAIT1(); }
        __syncthreads();
        if (c + 2 < nchunks) load_chunk(c + 2);

        const uint32_t base = sb + (c % NSTAGE) * STAGE_BYTES;
        const uint32_t sAh = base;
        const uint32_t sAl = base + TILE_BYTES;
        const uint32_t sBh = base + 2 * TILE_BYTES;
        const uint32_t sBl = base + 3 * TILE_BYTES;

#pragma unroll
        for (int ks = 0; ks < 2; ks++) {
            const int k = ks * 16;
            // A fragments (hi, lo): 2 m-tiles each
            const uint32_t aoff =
                (uint32_t)(wm + (lane & 15)) * (RSTRIDE * 2) +
                (uint32_t)(k + ((lane >> 4) << 3)) * 2;
            uint32_t ah[2][4], al[2][4];
#pragma unroll
            for (int mi = 0; mi < 2; mi++) {
                const uint32_t d = aoff + mi * 16 * (RSTRIDE * 2);
                LDMATRIX_X4(ah[mi][0], ah[mi][1], ah[mi][2], ah[mi][3], sAh + d);
                LDMATRIX_X4(al[mi][0], al[mi][1], al[mi][2], al[mi][3], sAl + d);
            }
            // B fragments (hi, lo): 2 n-pairs each (each x4 = two 8-wide n tiles)
            const uint32_t boff =
                (uint32_t)(wn + ((lane >> 4) << 3) + (lane & 7)) * (RSTRIDE * 2) +
                (uint32_t)(k + (((lane >> 3) & 1) << 3)) * 2;
            uint32_t bh[2][4], bl[2][4];
#pragma unroll
            for (int np = 0; np < 2; np++) {
                const uint32_t d = boff + np * 16 * (RSTRIDE * 2);
                LDMATRIX_X4(bh[np][0], bh[np][1], bh[np][2], bh[np][3], sBh + d);
                LDMATRIX_X4(bl[np][0], bl[np][1], bl[np][2], bl[np][3], sBl + d);
            }
            // Term-outer MMA order: same-accumulator reuse distance = 8 MMAs
#pragma unroll
            for (int mi = 0; mi < 2; mi++)
#pragma unroll
                for (int ni = 0; ni < 4; ni++) {
                    const int np = ni >> 1, q = (ni & 1) * 2;
                    MMA16816(acc[mi][ni], ah[mi], bh[np][q], bh[np][q + 1]);
                }
#pragma unroll
            for (int mi = 0; mi < 2; mi++)
#pragma unroll
                for (int ni = 0; ni < 4; ni++) {
                    const int np = ni >> 1, q = (ni & 1) * 2;
                    MMA16816(acc[mi][ni], ah[mi], bl[np][q], bl[np][q + 1]);
                }
#pragma unroll
            for (int mi = 0; mi < 2; mi++)
#pragma unroll
                for (int ni = 0; ni < 4; ni++) {
                    const int np = ni >> 1, q = (ni & 1) * 2;
                    MMA16816(acc[mi][ni], al[mi], bh[np][q], bh[np][q + 1]);
                }
        }
    }

    // ---- epilogue: direct register -> gmem, fused ops ----
#pragma unroll
    for (int mi = 0; mi < 2; mi++) {
#pragma unroll
        for (int ni = 0; ni < 4; ni++) {
            const int col = colBase + wn + ni * 8 + (lane & 3) * 2;
#pragma unroll
            for (int hf = 0; hf < 2; hf++) {
                const int row = rowBase + wm + mi * 16 + (lane >> 2) + hf * 8;
                const float c0 = acc[mi][ni][hf * 2 + 0];
                const float c1 = acc[mi][ni][hf * 2 + 1];
                const size_t oidx = (size_t)row * ldout + col;
                if (MODE == 0) {
                    float2 r;
                    r.x = tanhf(c0 + bias[col]);
                    r.y = tanhf(c1 + bias[col + 1]);
                    *(float2*)&out[oidx] = r;
                } else if (MODE == 1) {
                    const size_t ii = (size_t)row * HSZ + col;
                    const float2 gv = *(const float2*)&graw[ii];
                    const float2 hv = *(const float2*)&hraw[ii];
                    const float t0 = tanhf(c0 + bias[col]);
                    const float t1 = tanhf(c1 + bias[col + 1]);
                    float2 hn;
                    hn.x = gv.x * t0 + (1.0f - gv.x) * hv.x;
                    hn.y = gv.y * t1 + (1.0f - gv.y) * hv.y;
                    *(float2*)&out[oidx] = hn;
                    __half h0, l0, h1, l1;
                    split16(hn.x, h0, l0);
                    split16(hn.y, h1, l1);
                    *(__half2*)&g_hn_hi[ii] = __halves2half2(h0, h1);
                    *(__half2*)&g_hn_lo[ii] = __halves2half2(l0, l1);
                } else {
                    float2 r;
                    r.x = c0 + bias[col];
                    r.y = c1 + bias[col + 1];
                    *(float2*)&out[oidx] = r;
                }
            }
        }
    }
}

// ---------------------------------------------------------------------------
// Launch
// ---------------------------------------------------------------------------
extern "C" void kernel_launch(void* const* d_in, const int* in_sizes, int n_in,
                              void* d_out, int out_size) {
    const float* x     = (const float*)d_in[0];
    const float* h     = (const float*)d_in[1];
    const float* g     = (const float*)d_in[2];
    const float* w_xh  = (const float*)d_in[3];
    const float* w_hh  = (const float*)d_in[4];
    const float* b_h   = (const float*)d_in[5];
    const float* w_gx  = (const float*)d_in[6];
    const float* w_gh  = (const float*)d_in[7];
    const float* b_g   = (const float*)d_in[8];
    const float* lin_w = (const float*)d_in[9];
    const float* lin_b = (const float*)d_in[10];

    float* o     = (float*)d_out;
    float* h_new = o + (size_t)BSZ * ISZ;
    float* g_new = h_new + (size_t)BSZ * HSZ;

    void *xh, *xl, *hh, *hl, *lh, *ll;
    void *gxh, *gxl, *ghh, *ghl, *xhh, *xhl, *hhh, *hhl;
    cudaGetSymbolAddress(&xh, g_x_hi);    cudaGetSymbolAddress(&xl, g_x_lo);
    cudaGetSymbolAddress(&hh, g_h_hi);    cudaGetSymbolAddress(&hl, g_h_lo);
    cudaGetSymbolAddress(&lh, g_linw_hi); cudaGetSymbolAddress(&ll, g_linw_lo);
    cudaGetSymbolAddress(&gxh, g_wgxT_hi); cudaGetSymbolAddress(&gxl, g_wgxT_lo);
    cudaGetSymbolAddress(&ghh, g_wghT_hi); cudaGetSymbolAddress(&ghl, g_wghT_lo);
    cudaGetSymbolAddress(&xhh, g_wxhT_hi); cudaGetSymbolAddress(&xhl, g_wxhT_lo);
    cudaGetSymbolAddress(&hhh, g_whhT_hi); cudaGetSymbolAddress(&hhl, g_whhT_lo);

    cudaFuncSetAttribute(gemm_f16_kernel<0>, cudaFuncAttributeMaxDynamicSharedMemorySize, SMEM_MAIN);
    cudaFuncSetAttribute(gemm_f16_kernel<1>, cudaFuncAttributeMaxDynamicSharedMemorySize, SMEM_MAIN);
    cudaFuncSetAttribute(gemm_f16_kernel<2>, cudaFuncAttributeMaxDynamicSharedMemorySize, SMEM_MAIN);

    // fp16 hi/lo splits (no transpose)
    split_kernel<<<(BSZ * ISZ / 4 + 255) / 256, 256>>>((const float4*)x, (__half2*)xh, (__half2*)xl, BSZ * ISZ / 4);
    split_kernel<<<(BSZ * HSZ / 4 + 255) / 256, 256>>>((const float4*)h, (__half2*)hh, (__half2*)hl, BSZ * HSZ / 4);
    split_kernel<<<(ISZ * HSZ / 4 + 255) / 256, 256>>>((const float4*)lin_w, (__half2*)lh, (__half2*)ll, ISZ * HSZ / 4);

    // weight transposes + splits ([K,N] -> [N,K])
    transpose_split<<<dim3(HSZ / 32, ISZ / 32), dim3(32, 8)>>>(w_gx, (__half*)gxh, (__half*)gxl, ISZ, HSZ);
    transpose_split<<<dim3(HSZ / 32, HSZ / 32), dim3(32, 8)>>>(w_gh, (__half*)ghh, (__half*)ghl, HSZ, HSZ);
    transpose_split<<<dim3(HSZ / 32, ISZ / 32), dim3(32, 8)>>>(w_xh, (__half*)xhh, (__half*)xhl, ISZ, HSZ);
    transpose_split<<<dim3(HSZ / 32, HSZ / 32), dim3(32, 8)>>>(w_hh, (__half*)hhh, (__half*)hhl, HSZ, HSZ);

    // GEMMs
    gemm_f16_kernel<0><<<dim3(HSZ / 128, BSZ / 128), NTH, SMEM_MAIN>>>(b_g, nullptr, nullptr, g_new);
    gemm_f16_kernel<1><<<dim3(HSZ / 128, BSZ / 128), NTH, SMEM_MAIN>>>(b_h, g, h, h_new);
    gemm_f16_kernel<2><<<dim3(ISZ / 128, BSZ / 128), NTH, SMEM_MAIN>>>(lin_b, nullptr, nullptr, o);
}

// round 5
// speedup vs baseline: 1.7747x; 1.7747x over previous
#include <cuda_runtime.h>
#include <cuda_fp16.h>
#include <math.h>
#include <cstdint>

#define BSZ 4096
#define ISZ 1024
#define HSZ 2048
#define NTH 512

// ---------------------------------------------------------------------------
// Device scratch: activations hi+lo, weights hi only
// ---------------------------------------------------------------------------
__device__ __half g_x_hi[BSZ * ISZ],  g_x_lo[BSZ * ISZ];
__device__ __half g_h_hi[BSZ * HSZ],  g_h_lo[BSZ * HSZ];
__device__ __half g_wgxT_hi[HSZ * ISZ];
__device__ __half g_wxhT_hi[HSZ * ISZ];
__device__ __half g_wghT_hi[HSZ * HSZ];
__device__ __half g_whhT_hi[HSZ * HSZ];
__device__ __half g_linw_hi[ISZ * HSZ];
__device__ __half g_hn_hi[BSZ * HSZ],  g_hn_lo[BSZ * HSZ];

// ---------------------------------------------------------------------------
// PTX helpers (sm_80-era only: must compile for plain sm_103 target)
// ---------------------------------------------------------------------------
__device__ __forceinline__ uint32_t smem_u32(const void* p) {
    uint32_t a;
    asm("{ .reg .u64 t; cvta.to.shared.u64 t, %1; cvt.u32.u64 %0, t; }"
        : "=r"(a) : "l"(p));
    return a;
}

#define CP16(dst, src) \
    asm volatile("cp.async.cg.shared.global [%0], [%1], 16;" :: "r"(dst), "l"(src))
#define CP_COMMIT() asm volatile("cp.async.commit_group;" ::: "memory")
#define CP_WAIT0()  asm volatile("cp.async.wait_group 0;" ::: "memory")
#define CP_WAIT1()  asm volatile("cp.async.wait_group 1;" ::: "memory")

#define LDMATRIX_X4(r0, r1, r2, r3, addr)                                   \
    asm volatile("ldmatrix.sync.aligned.m8n8.x4.shared.b16 {%0,%1,%2,%3}, [%4];" \
                 : "=r"(r0), "=r"(r1), "=r"(r2), "=r"(r3) : "r"(addr))

#define MMA16816(c, a, b0, b1)                                              \
    asm volatile("mma.sync.aligned.m16n8k16.row.col.f32.f16.f16.f32 "       \
                 "{%0,%1,%2,%3}, {%4,%5,%6,%7}, {%8,%9}, {%0,%1,%2,%3};"    \
                 : "+f"((c)[0]), "+f"((c)[1]), "+f"((c)[2]), "+f"((c)[3])   \
                 : "r"((a)[0]), "r"((a)[1]), "r"((a)[2]), "r"((a)[3]),      \
                   "r"(b0), "r"(b1))

// ---------------------------------------------------------------------------
// Prep kernels
// ---------------------------------------------------------------------------
__device__ __forceinline__ void split16(float v, __half& hi, __half& lo) {
    __half h = __float2half_rn(v);
    hi = h;
    lo = __float2half_rn(v - __half2float(h));
}

__global__ void split_kernel(const float4* __restrict__ src,
                             __half2* __restrict__ hi, __half2* __restrict__ lo,
                             int n4) {
    int i = blockIdx.x * blockDim.x + threadIdx.x;
    if (i < n4) {
        float4 v = src[i];
        __half hx, lx, hy, ly, hz, lz, hw, lw;
        split16(v.x, hx, lx); split16(v.y, hy, ly);
        split16(v.z, hz, lz); split16(v.w, hw, lw);
        hi[2 * i]     = __halves2half2(hx, hy);
        hi[2 * i + 1] = __halves2half2(hz, hw);
        lo[2 * i]     = __halves2half2(lx, ly);
        lo[2 * i + 1] = __halves2half2(lz, lw);
    }
}

// fp32 -> fp16 hi only
__global__ void split_hi_kernel(const float4* __restrict__ src,
                                __half2* __restrict__ hi, int n4) {
    int i = blockIdx.x * blockDim.x + threadIdx.x;
    if (i < n4) {
        float4 v = src[i];
        hi[2 * i]     = __halves2half2(__float2half_rn(v.x), __float2half_rn(v.y));
        hi[2 * i + 1] = __halves2half2(__float2half_rn(v.z), __float2half_rn(v.w));
    }
}

// src [K,N] row-major -> dst [N,K] fp16 (hi only)
__global__ void transpose_hi(const float* __restrict__ src,
                             __half* __restrict__ dhi, int K, int N) {
    __shared__ float tile[32][33];
    int nb = blockIdx.x * 32, kb = blockIdx.y * 32;
    int tx = threadIdx.x, ty = threadIdx.y;
#pragma unroll
    for (int r = 0; r < 32; r += 8)
        tile[ty + r][tx] = src[(size_t)(kb + ty + r) * N + nb + tx];
    __syncthreads();
#pragma unroll
    for (int r = 0; r < 32; r += 8) {
        float v = tile[tx][ty + r];
        dhi[(size_t)(nb + ty + r) * K + kb + tx] = __float2half_rn(v);
    }
}

// ---------------------------------------------------------------------------
// Main GEMM: mma.sync m16n8k16 fp16, 2-term (activation hi/lo x weight hi).
//   MODE 0: g_new = tanh(x@w_gx + h@w_gh + b)
//   MODE 1: h_new = g*tanh(x@w_xh + h@w_hh + b) + (1-g)*h  (+ split hn out)
//   MODE 2: o = h_new @ lin_w^T + b
// Tiles: BM=BN=128, BK=32. 16 warps, warp tile 32x32.
// ---------------------------------------------------------------------------
#define RSTRIDE 40                      // halves per smem row (32 + 8 pad)
#define TILE_BYTES (128 * RSTRIDE * 2)  // 10240
#define STAGE_BYTES (3 * TILE_BYTES)    // Ah, Al, Bh = 30720
#define NSTAGE 3
#define SMEM_MAIN (NSTAGE * STAGE_BYTES)

template <int MODE>
__global__ __launch_bounds__(NTH, 1) void gemm_f16_kernel(
    const float* __restrict__ bias,
    const float* __restrict__ graw,
    const float* __restrict__ hraw,
    float* __restrict__ out)
{
    extern __shared__ __align__(128) unsigned char dsm[];
    const uint32_t sb = smem_u32(dsm);
    const int tid = threadIdx.x;
    const int wid = tid >> 5, lane = tid & 31;
    const int rowBase = blockIdx.y * 128;
    const int colBase = blockIdx.x * 128;
    const int nchunks = (MODE == 2) ? (HSZ / 32) : ((ISZ + HSZ) / 32);
    const int ldout = (MODE == 2) ? ISZ : HSZ;

    const int wm = (wid >> 2) * 32;   // warp m offset
    const int wn = (wid & 3) * 32;    // warp n offset

    float acc[2][4][4];
#pragma unroll
    for (int mi = 0; mi < 2; mi++)
#pragma unroll
        for (int ni = 0; ni < 4; ni++)
#pragma unroll
            for (int q = 0; q < 4; q++) acc[mi][ni][q] = 0.0f;

    // ---- chunk loader: 3 tiles x 128 rows x 64B, cp.async 16B, 3 per thread
    auto load_chunk = [&](int c) {
        const int k0 = c * 32;
        const __half *Ah, *Al, *Bh;
        int lda, ldb, kk;
        if (MODE == 2) {
            Ah = g_hn_hi; Al = g_hn_lo; lda = HSZ; kk = k0;
            Bh = g_linw_hi; ldb = HSZ;
        } else if (k0 < ISZ) {
            Ah = g_x_hi; Al = g_x_lo; lda = ISZ; kk = k0;
            Bh = (MODE == 0) ? g_wgxT_hi : g_wxhT_hi; ldb = ISZ;
        } else {
            Ah = g_h_hi; Al = g_h_lo; lda = HSZ; kk = k0 - ISZ;
            Bh = (MODE == 0) ? g_wghT_hi : g_whhT_hi; ldb = HSZ;
        }
        const uint32_t base = sb + (c % NSTAGE) * STAGE_BYTES;
        const int row = tid >> 2, kc = tid & 3;
        const uint32_t soff = (uint32_t)row * (RSTRIDE * 2) + kc * 16;
        CP16(base + soff,
             Ah + (size_t)(rowBase + row) * lda + kk + kc * 8);
        CP16(base + TILE_BYTES + soff,
             Al + (size_t)(rowBase + row) * lda + kk + kc * 8);
        CP16(base + 2 * TILE_BYTES + soff,
             Bh + (size_t)(colBase + row) * ldb + kk + kc * 8);
        CP_COMMIT();
    };

    load_chunk(0);
    load_chunk(1);

    for (int c = 0; c < nchunks; c++) {
        if (c == nchunks - 1) { CP_WAIT0(); } else { CP_WAIT1(); }
        __syncthreads();
        if (c + 2 < nchunks) load_chunk(c + 2);

        const uint32_t base = sb + (c % NSTAGE) * STAGE_BYTES;
        const uint32_t sAh = base;
        const uint32_t sAl = base + TILE_BYTES;
        const uint32_t sBh = base + 2 * TILE_BYTES;

#pragma unroll
        for (int ks = 0; ks < 2; ks++) {
            const int k = ks * 16;
            // A fragments (hi, lo): 2 m-tiles each
            const uint32_t aoff =
                (uint32_t)(wm + (lane & 15)) * (RSTRIDE * 2) +
                (uint32_t)(k + ((lane >> 4) << 3)) * 2;
            uint32_t ah[2][4], al[2][4];
#pragma unroll
            for (int mi = 0; mi < 2; mi++) {
                const uint32_t d = aoff + mi * 16 * (RSTRIDE * 2);
                LDMATRIX_X4(ah[mi][0], ah[mi][1], ah[mi][2], ah[mi][3], sAh + d);
                LDMATRIX_X4(al[mi][0], al[mi][1], al[mi][2], al[mi][3], sAl + d);
            }
            // B fragments (hi only): 2 n-pairs
            const uint32_t boff =
                (uint32_t)(wn + ((lane >> 4) << 3) + (lane & 7)) * (RSTRIDE * 2) +
                (uint32_t)(k + (((lane >> 3) & 1) << 3)) * 2;
            uint32_t bh[2][4];
#pragma unroll
            for (int np = 0; np < 2; np++) {
                const uint32_t d = boff + np * 16 * (RSTRIDE * 2);
                LDMATRIX_X4(bh[np][0], bh[np][1], bh[np][2], bh[np][3], sBh + d);
            }
            // 2-term, term-outer (RAW distance 8)
#pragma unroll
            for (int mi = 0; mi < 2; mi++)
#pragma unroll
                for (int ni = 0; ni < 4; ni++) {
                    const int np = ni >> 1, q = (ni & 1) * 2;
                    MMA16816(acc[mi][ni], ah[mi], bh[np][q], bh[np][q + 1]);
                }
#pragma unroll
            for (int mi = 0; mi < 2; mi++)
#pragma unroll
                for (int ni = 0; ni < 4; ni++) {
                    const int np = ni >> 1, q = (ni & 1) * 2;
                    MMA16816(acc[mi][ni], al[mi], bh[np][q], bh[np][q + 1]);
                }
        }
    }

    // ---- epilogue: direct register -> gmem, fused ops ----
#pragma unroll
    for (int mi = 0; mi < 2; mi++) {
#pragma unroll
        for (int ni = 0; ni < 4; ni++) {
            const int col = colBase + wn + ni * 8 + (lane & 3) * 2;
#pragma unroll
            for (int hf = 0; hf < 2; hf++) {
                const int row = rowBase + wm + mi * 16 + (lane >> 2) + hf * 8;
                const float c0 = acc[mi][ni][hf * 2 + 0];
                const float c1 = acc[mi][ni][hf * 2 + 1];
                const size_t oidx = (size_t)row * ldout + col;
                if (MODE == 0) {
                    float2 r;
                    r.x = tanhf(c0 + bias[col]);
                    r.y = tanhf(c1 + bias[col + 1]);
                    *(float2*)&out[oidx] = r;
                } else if (MODE == 1) {
                    const size_t ii = (size_t)row * HSZ + col;
                    const float2 gv = *(const float2*)&graw[ii];
                    const float2 hv = *(const float2*)&hraw[ii];
                    const float t0 = tanhf(c0 + bias[col]);
                    const float t1 = tanhf(c1 + bias[col + 1]);
                    float2 hn;
                    hn.x = gv.x * t0 + (1.0f - gv.x) * hv.x;
                    hn.y = gv.y * t1 + (1.0f - gv.y) * hv.y;
                    *(float2*)&out[oidx] = hn;
                    __half h0, l0, h1, l1;
                    split16(hn.x, h0, l0);
                    split16(hn.y, h1, l1);
                    *(__half2*)&g_hn_hi[ii] = __halves2half2(h0, h1);
                    *(__half2*)&g_hn_lo[ii] = __halves2half2(l0, l1);
                } else {
                    float2 r;
                    r.x = c0 + bias[col];
                    r.y = c1 + bias[col + 1];
                    *(float2*)&out[oidx] = r;
                }
            }
        }
    }
}

// ---------------------------------------------------------------------------
// Launch
// ---------------------------------------------------------------------------
extern "C" void kernel_launch(void* const* d_in, const int* in_sizes, int n_in,
                              void* d_out, int out_size) {
    const float* x     = (const float*)d_in[0];
    const float* h     = (const float*)d_in[1];
    const float* g     = (const float*)d_in[2];
    const float* w_xh  = (const float*)d_in[3];
    const float* w_hh  = (const float*)d_in[4];
    const float* b_h   = (const float*)d_in[5];
    const float* w_gx  = (const float*)d_in[6];
    const float* w_gh  = (const float*)d_in[7];
    const float* b_g   = (const float*)d_in[8];
    const float* lin_w = (const float*)d_in[9];
    const float* lin_b = (const float*)d_in[10];

    float* o     = (float*)d_out;
    float* h_new = o + (size_t)BSZ * ISZ;
    float* g_new = h_new + (size_t)BSZ * HSZ;

    void *xh, *xl, *hh, *hl, *lh;
    void *gxh, *ghh, *xhh, *hhh;
    cudaGetSymbolAddress(&xh, g_x_hi);    cudaGetSymbolAddress(&xl, g_x_lo);
    cudaGetSymbolAddress(&hh, g_h_hi);    cudaGetSymbolAddress(&hl, g_h_lo);
    cudaGetSymbolAddress(&lh, g_linw_hi);
    cudaGetSymbolAddress(&gxh, g_wgxT_hi);
    cudaGetSymbolAddress(&ghh, g_wghT_hi);
    cudaGetSymbolAddress(&xhh, g_wxhT_hi);
    cudaGetSymbolAddress(&hhh, g_whhT_hi);

    cudaFuncSetAttribute(gemm_f16_kernel<0>, cudaFuncAttributeMaxDynamicSharedMemorySize, SMEM_MAIN);
    cudaFuncSetAttribute(gemm_f16_kernel<1>, cudaFuncAttributeMaxDynamicSharedMemorySize, SMEM_MAIN);
    cudaFuncSetAttribute(gemm_f16_kernel<2>, cudaFuncAttributeMaxDynamicSharedMemorySize, SMEM_MAIN);

    // activation splits (hi+lo), weight hi-only
    split_kernel<<<(BSZ * ISZ / 4 + 255) / 256, 256>>>((const float4*)x, (__half2*)xh, (__half2*)xl, BSZ * ISZ / 4);
    split_kernel<<<(BSZ * HSZ / 4 + 255) / 256, 256>>>((const float4*)h, (__half2*)hh, (__half2*)hl, BSZ * HSZ / 4);
    split_hi_kernel<<<(ISZ * HSZ / 4 + 255) / 256, 256>>>((const float4*)lin_w, (__half2*)lh, ISZ * HSZ / 4);

    // weight transposes ([K,N] -> [N,K], hi only)
    transpose_hi<<<dim3(HSZ / 32, ISZ / 32), dim3(32, 8)>>>(w_gx, (__half*)gxh, ISZ, HSZ);
    transpose_hi<<<dim3(HSZ / 32, HSZ / 32), dim3(32, 8)>>>(w_gh, (__half*)ghh, HSZ, HSZ);
    transpose_hi<<<dim3(HSZ / 32, ISZ / 32), dim3(32, 8)>>>(w_xh, (__half*)xhh, ISZ, HSZ);
    transpose_hi<<<dim3(HSZ / 32, HSZ / 32), dim3(32, 8)>>>(w_hh, (__half*)hhh, HSZ, HSZ);

    // GEMMs
    gemm_f16_kernel<0><<<dim3(HSZ / 128, BSZ / 128), NTH, SMEM_MAIN>>>(b_g, nullptr, nullptr, g_new);
    gemm_f16_kernel<1><<<dim3(HSZ / 128, BSZ / 128), NTH, SMEM_MAIN>>>(b_h, g, h, h_new);
    gemm_f16_kernel<2><<<dim3(ISZ / 128, BSZ / 128), NTH, SMEM_MAIN>>>(lin_b, nullptr, nullptr, o);
}

// round 6
// speedup vs baseline: 2.9250x; 1.6482x over previous
#include <cuda_runtime.h>
#include <cuda_fp16.h>
#include <math.h>
#include <cstdint>

#define BSZ 4096
#define ISZ 1024
#define HSZ 2048
#define NTH 512

// ---------------------------------------------------------------------------
// Device scratch: single fp16 plane for everything
// ---------------------------------------------------------------------------
__device__ __half g_x16[BSZ * ISZ];
__device__ __half g_h16[BSZ * HSZ];
__device__ __half g_wgxT[HSZ * ISZ];
__device__ __half g_wxhT[HSZ * ISZ];
__device__ __half g_wghT[HSZ * HSZ];
__device__ __half g_whhT[HSZ * HSZ];
__device__ __half g_linw[ISZ * HSZ];
__device__ __half g_hn16[BSZ * HSZ];

// ---------------------------------------------------------------------------
// PTX helpers (sm_80-era only: must compile for plain sm_103 target)
// ---------------------------------------------------------------------------
__device__ __forceinline__ uint32_t smem_u32(const void* p) {
    uint32_t a;
    asm("{ .reg .u64 t; cvta.to.shared.u64 t, %1; cvt.u32.u64 %0, t; }"
        : "=r"(a) : "l"(p));
    return a;
}

#define CP16(dst, src) \
    asm volatile("cp.async.cg.shared.global [%0], [%1], 16;" :: "r"(dst), "l"(src))
#define CP_COMMIT() asm volatile("cp.async.commit_group;" ::: "memory")
#define CP_WAIT0()  asm volatile("cp.async.wait_group 0;" ::: "memory")
#define CP_WAIT1()  asm volatile("cp.async.wait_group 1;" ::: "memory")

#define LDMATRIX_X4(r0, r1, r2, r3, addr)                                   \
    asm volatile("ldmatrix.sync.aligned.m8n8.x4.shared.b16 {%0,%1,%2,%3}, [%4];" \
                 : "=r"(r0), "=r"(r1), "=r"(r2), "=r"(r3) : "r"(addr))

#define MMA16816(c, a, b0, b1)                                              \
    asm volatile("mma.sync.aligned.m16n8k16.row.col.f32.f16.f16.f32 "       \
                 "{%0,%1,%2,%3}, {%4,%5,%6,%7}, {%8,%9}, {%0,%1,%2,%3};"    \
                 : "+f"((c)[0]), "+f"((c)[1]), "+f"((c)[2]), "+f"((c)[3])   \
                 : "r"((a)[0]), "r"((a)[1]), "r"((a)[2]), "r"((a)[3]),      \
                   "r"(b0), "r"(b1))

// ---------------------------------------------------------------------------
// Prep kernels: fp32 -> fp16 convert (and weight transpose)
// ---------------------------------------------------------------------------
__global__ void conv_kernel(const float4* __restrict__ src,
                            __half2* __restrict__ dst, int n4) {
    int i = blockIdx.x * blockDim.x + threadIdx.x;
    if (i < n4) {
        float4 v = src[i];
        dst[2 * i]     = __halves2half2(__float2half_rn(v.x), __float2half_rn(v.y));
        dst[2 * i + 1] = __halves2half2(__float2half_rn(v.z), __float2half_rn(v.w));
    }
}

// src [K,N] row-major -> dst [N,K] fp16
__global__ void transpose_conv(const float* __restrict__ src,
                               __half* __restrict__ dst, int K, int N) {
    __shared__ float tile[32][33];
    int nb = blockIdx.x * 32, kb = blockIdx.y * 32;
    int tx = threadIdx.x, ty = threadIdx.y;
#pragma unroll
    for (int r = 0; r < 32; r += 8)
        tile[ty + r][tx] = src[(size_t)(kb + ty + r) * N + nb + tx];
    __syncthreads();
#pragma unroll
    for (int r = 0; r < 32; r += 8) {
        float v = tile[tx][ty + r];
        dst[(size_t)(nb + ty + r) * K + kb + tx] = __float2half_rn(v);
    }
}

// ---------------------------------------------------------------------------
// Main GEMM: mma.sync m16n8k16 fp16, single term.
//   MODE 0: g_new = tanh(x@w_gx + h@w_gh + b)
//   MODE 1: h_new = g*tanh(x@w_xh + h@w_hh + b) + (1-g)*h  (+ fp16 hn out)
//   MODE 2: o = h_new @ lin_w^T + b
// Tiles: BM=BN=128, BK=32. 16 warps, warp tile 32x32.
// ---------------------------------------------------------------------------
#define RSTRIDE 40                      // halves per smem row (32 + 8 pad)
#define TILE_BYTES (128 * RSTRIDE * 2)  // 10240
#define STAGE_BYTES (2 * TILE_BYTES)    // A, B = 20480
#define NSTAGE 3
#define SMEM_MAIN (NSTAGE * STAGE_BYTES)

template <int MODE>
__global__ __launch_bounds__(NTH, 1) void gemm_f16_kernel(
    const float* __restrict__ bias,
    const float* __restrict__ graw,
    const float* __restrict__ hraw,
    float* __restrict__ out)
{
    extern __shared__ __align__(128) unsigned char dsm[];
    const uint32_t sb = smem_u32(dsm);
    const int tid = threadIdx.x;
    const int wid = tid >> 5, lane = tid & 31;
    const int rowBase = blockIdx.y * 128;
    const int colBase = blockIdx.x * 128;
    const int nchunks = (MODE == 2) ? (HSZ / 32) : ((ISZ + HSZ) / 32);
    const int ldout = (MODE == 2) ? ISZ : HSZ;

    const int wm = (wid >> 2) * 32;   // warp m offset
    const int wn = (wid & 3) * 32;    // warp n offset

    float acc[2][4][4];
#pragma unroll
    for (int mi = 0; mi < 2; mi++)
#pragma unroll
        for (int ni = 0; ni < 4; ni++)
#pragma unroll
            for (int q = 0; q < 4; q++) acc[mi][ni][q] = 0.0f;

    // ---- chunk loader: 2 tiles x 128 rows x 64B, cp.async 16B, 2/thread ----
    auto load_chunk = [&](int c) {
        const int k0 = c * 32;
        const __half *A, *B;
        int lda, ldb, kk;
        if (MODE == 2) {
            A = g_hn16; lda = HSZ; kk = k0;
            B = g_linw; ldb = HSZ;
        } else if (k0 < ISZ) {
            A = g_x16; lda = ISZ; kk = k0;
            B = (MODE == 0) ? g_wgxT : g_wxhT; ldb = ISZ;
        } else {
            A = g_h16; lda = HSZ; kk = k0 - ISZ;
            B = (MODE == 0) ? g_wghT : g_whhT; ldb = HSZ;
        }
        const uint32_t base = sb + (c % NSTAGE) * STAGE_BYTES;
        const int row = tid >> 2, kc = tid & 3;
        const uint32_t soff = (uint32_t)row * (RSTRIDE * 2) + kc * 16;
        CP16(base + soff,
             A + (size_t)(rowBase + row) * lda + kk + kc * 8);
        CP16(base + TILE_BYTES + soff,
             B + (size_t)(colBase + row) * ldb + kk + kc * 8);
        CP_COMMIT();
    };

    load_chunk(0);
    load_chunk(1);

    for (int c = 0; c < nchunks; c++) {
        if (c == nchunks - 1) { CP_WAIT0(); } else { CP_WAIT1(); }
        __syncthreads();
        if (c + 2 < nchunks) load_chunk(c + 2);

        const uint32_t base = sb + (c % NSTAGE) * STAGE_BYTES;
        const uint32_t sA = base;
        const uint32_t sB = base + TILE_BYTES;

#pragma unroll
        for (int ks = 0; ks < 2; ks++) {
            const int k = ks * 16;
            // A fragments: 2 m-tiles
            const uint32_t aoff =
                (uint32_t)(wm + (lane & 15)) * (RSTRIDE * 2) +
                (uint32_t)(k + ((lane >> 4) << 3)) * 2;
            uint32_t af[2][4];
#pragma unroll
            for (int mi = 0; mi < 2; mi++) {
                const uint32_t d = aoff + mi * 16 * (RSTRIDE * 2);
                LDMATRIX_X4(af[mi][0], af[mi][1], af[mi][2], af[mi][3], sA + d);
            }
            // B fragments: 2 n-pairs (each x4 = two 8-wide n tiles)
            const uint32_t boff =
                (uint32_t)(wn + ((lane >> 4) << 3) + (lane & 7)) * (RSTRIDE * 2) +
                (uint32_t)(k + (((lane >> 3) & 1) << 3)) * 2;
            uint32_t bf[2][4];
#pragma unroll
            for (int np = 0; np < 2; np++) {
                const uint32_t d = boff + np * 16 * (RSTRIDE * 2);
                LDMATRIX_X4(bf[np][0], bf[np][1], bf[np][2], bf[np][3], sB + d);
            }
            // 8 MMAs, all-independent accumulators (RAW distance 8)
#pragma unroll
            for (int mi = 0; mi < 2; mi++)
#pragma unroll
                for (int ni = 0; ni < 4; ni++) {
                    const int np = ni >> 1, q = (ni & 1) * 2;
                    MMA16816(acc[mi][ni], af[mi], bf[np][q], bf[np][q + 1]);
                }
        }
    }

    // ---- epilogue: direct register -> gmem, fused ops ----
#pragma unroll
    for (int mi = 0; mi < 2; mi++) {
#pragma unroll
        for (int ni = 0; ni < 4; ni++) {
            const int col = colBase + wn + ni * 8 + (lane & 3) * 2;
#pragma unroll
            for (int hf = 0; hf < 2; hf++) {
                const int row = rowBase + wm + mi * 16 + (lane >> 2) + hf * 8;
                const float c0 = acc[mi][ni][hf * 2 + 0];
                const float c1 = acc[mi][ni][hf * 2 + 1];
                const size_t oidx = (size_t)row * ldout + col;
                if (MODE == 0) {
                    float2 r;
                    r.x = tanhf(c0 + bias[col]);
                    r.y = tanhf(c1 + bias[col + 1]);
                    *(float2*)&out[oidx] = r;
                } else if (MODE == 1) {
                    const size_t ii = (size_t)row * HSZ + col;
                    const float2 gv = *(const float2*)&graw[ii];
                    const float2 hv = *(const float2*)&hraw[ii];
                    const float t0 = tanhf(c0 + bias[col]);
                    const float t1 = tanhf(c1 + bias[col + 1]);
                    float2 hn;
                    hn.x = gv.x * t0 + (1.0f - gv.x) * hv.x;
                    hn.y = gv.y * t1 + (1.0f - gv.y) * hv.y;
                    *(float2*)&out[oidx] = hn;
                    *(__half2*)&g_hn16[ii] =
                        __halves2half2(__float2half_rn(hn.x), __float2half_rn(hn.y));
                } else {
                    float2 r;
                    r.x = c0 + bias[col];
                    r.y = c1 + bias[col + 1];
                    *(float2*)&out[oidx] = r;
                }
            }
        }
    }
}

// ---------------------------------------------------------------------------
// Launch
// ---------------------------------------------------------------------------
extern "C" void kernel_launch(void* const* d_in, const int* in_sizes, int n_in,
                              void* d_out, int out_size) {
    const float* x     = (const float*)d_in[0];
    const float* h     = (const float*)d_in[1];
    const float* g     = (const float*)d_in[2];
    const float* w_xh  = (const float*)d_in[3];
    const float* w_hh  = (const float*)d_in[4];
    const float* b_h   = (const float*)d_in[5];
    const float* w_gx  = (const float*)d_in[6];
    const float* w_gh  = (const float*)d_in[7];
    const float* b_g   = (const float*)d_in[8];
    const float* lin_w = (const float*)d_in[9];
    const float* lin_b = (const float*)d_in[10];

    float* o     = (float*)d_out;
    float* h_new = o + (size_t)BSZ * ISZ;
    float* g_new = h_new + (size_t)BSZ * HSZ;

    void *x16, *h16, *lw;
    void *gxT, *ghT, *xhT, *hhT;
    cudaGetSymbolAddress(&x16, g_x16);
    cudaGetSymbolAddress(&h16, g_h16);
    cudaGetSymbolAddress(&lw, g_linw);
    cudaGetSymbolAddress(&gxT, g_wgxT);
    cudaGetSymbolAddress(&ghT, g_wghT);
    cudaGetSymbolAddress(&xhT, g_wxhT);
    cudaGetSymbolAddress(&hhT, g_whhT);

    cudaFuncSetAttribute(gemm_f16_kernel<0>, cudaFuncAttributeMaxDynamicSharedMemorySize, SMEM_MAIN);
    cudaFuncSetAttribute(gemm_f16_kernel<1>, cudaFuncAttributeMaxDynamicSharedMemorySize, SMEM_MAIN);
    cudaFuncSetAttribute(gemm_f16_kernel<2>, cudaFuncAttributeMaxDynamicSharedMemorySize, SMEM_MAIN);

    // fp32 -> fp16 converts
    conv_kernel<<<(BSZ * ISZ / 4 + 255) / 256, 256>>>((const float4*)x, (__half2*)x16, BSZ * ISZ / 4);
    conv_kernel<<<(BSZ * HSZ / 4 + 255) / 256, 256>>>((const float4*)h, (__half2*)h16, BSZ * HSZ / 4);
    conv_kernel<<<(ISZ * HSZ / 4 + 255) / 256, 256>>>((const float4*)lin_w, (__half2*)lw, ISZ * HSZ / 4);

    // weight transposes ([K,N] -> [N,K])
    transpose_conv<<<dim3(HSZ / 32, ISZ / 32), dim3(32, 8)>>>(w_gx, (__half*)gxT, ISZ, HSZ);
    transpose_conv<<<dim3(HSZ / 32, HSZ / 32), dim3(32, 8)>>>(w_gh, (__half*)ghT, HSZ, HSZ);
    transpose_conv<<<dim3(HSZ / 32, ISZ / 32), dim3(32, 8)>>>(w_xh, (__half*)xhT, ISZ, HSZ);
    transpose_conv<<<dim3(HSZ / 32, HSZ / 32), dim3(32, 8)>>>(w_hh, (__half*)hhT, HSZ, HSZ);

    // GEMMs
    gemm_f16_kernel<0><<<dim3(HSZ / 128, BSZ / 128), NTH, SMEM_MAIN>>>(b_g, nullptr, nullptr, g_new);
    gemm_f16_kernel<1><<<dim3(HSZ / 128, BSZ / 128), NTH, SMEM_MAIN>>>(b_h, g, h, h_new);
    gemm_f16_kernel<2><<<dim3(ISZ / 128, BSZ / 128), NTH, SMEM_MAIN>>>(lin_b, nullptr, nullptr, o);
}

// round 7
// speedup vs baseline: 3.3527x; 1.1462x over previous
#include <cuda_runtime.h>
#include <cuda_fp16.h>
#include <math.h>
#include <cstdint>

#define BSZ 4096
#define ISZ 1024
#define HSZ 2048
#define NTH 256

// ---------------------------------------------------------------------------
// Device scratch: fp16 planes (weights kept in original [K,N] layout)
// ---------------------------------------------------------------------------
__device__ __half g_x16[BSZ * ISZ];
__device__ __half g_h16[BSZ * HSZ];
__device__ __half g_wgx[ISZ * HSZ];   // [K=I, N=H]
__device__ __half g_wgh[HSZ * HSZ];   // [K=H, N=H]
__device__ __half g_wxh[ISZ * HSZ];
__device__ __half g_whh[HSZ * HSZ];
__device__ __half g_linw[ISZ * HSZ];  // [N=I, K=H] (already B-layout)
__device__ __half g_hn16[BSZ * HSZ];

// ---------------------------------------------------------------------------
// PTX helpers (sm_80-era only: must compile for plain sm_103 target)
// ---------------------------------------------------------------------------
__device__ __forceinline__ uint32_t smem_u32(const void* p) {
    uint32_t a;
    asm("{ .reg .u64 t; cvta.to.shared.u64 t, %1; cvt.u32.u64 %0, t; }"
        : "=r"(a) : "l"(p));
    return a;
}

#define CP16(dst, src) \
    asm volatile("cp.async.cg.shared.global [%0], [%1], 16;" :: "r"(dst), "l"(src))
#define CP_COMMIT() asm volatile("cp.async.commit_group;" ::: "memory")
#define CP_WAIT0()  asm volatile("cp.async.wait_group 0;" ::: "memory")
#define CP_WAIT1()  asm volatile("cp.async.wait_group 1;" ::: "memory")

#define LDMATRIX_X4(r0, r1, r2, r3, addr)                                   \
    asm volatile("ldmatrix.sync.aligned.m8n8.x4.shared.b16 {%0,%1,%2,%3}, [%4];" \
                 : "=r"(r0), "=r"(r1), "=r"(r2), "=r"(r3) : "r"(addr))

#define LDMATRIX_X4_T(r0, r1, r2, r3, addr)                                 \
    asm volatile("ldmatrix.sync.aligned.m8n8.x4.trans.shared.b16 {%0,%1,%2,%3}, [%4];" \
                 : "=r"(r0), "=r"(r1), "=r"(r2), "=r"(r3) : "r"(addr))

#define MMA16816(c, a, b0, b1)                                              \
    asm volatile("mma.sync.aligned.m16n8k16.row.col.f32.f16.f16.f32 "       \
                 "{%0,%1,%2,%3}, {%4,%5,%6,%7}, {%8,%9}, {%0,%1,%2,%3};"    \
                 : "+f"((c)[0]), "+f"((c)[1]), "+f"((c)[2]), "+f"((c)[3])   \
                 : "r"((a)[0]), "r"((a)[1]), "r"((a)[2]), "r"((a)[3]),      \
                   "r"(b0), "r"(b1))

// ---------------------------------------------------------------------------
// Prep: fp32 -> fp16 streaming convert
// ---------------------------------------------------------------------------
__global__ void conv_kernel(const float4* __restrict__ src,
                            __half2* __restrict__ dst, int n4) {
    int i = blockIdx.x * blockDim.x + threadIdx.x;
    if (i < n4) {
        float4 v = src[i];
        dst[2 * i]     = __halves2half2(__float2half_rn(v.x), __float2half_rn(v.y));
        dst[2 * i + 1] = __halves2half2(__float2half_rn(v.z), __float2half_rn(v.w));
    }
}

// ---------------------------------------------------------------------------
// Main GEMM: mma.sync m16n8k16 fp16, single term.
//  BM=64, BN=128, BK=32; 8 warps (warp tile 32x32); 3-stage cp.async.
//  BTRANS=1: B source is [K,N] (gate weights), loaded k-row-major,
//            fragments via ldmatrix.trans.
//  BTRANS=0: B source is [N,K] (lin_w / h_new-style), non-trans path.
//   MODE 0: g_new = tanh(x@w_gx + h@w_gh + b)
//   MODE 1: h_new = g*tanh(x@w_xh + h@w_hh + b) + (1-g)*h  (+ fp16 hn out)
//   MODE 2: o = h_new @ lin_w^T + b
// ---------------------------------------------------------------------------
#define A_RSTRIDE 80                       // bytes per A smem row (32h + 8 pad)
#define A_BYTES (64 * A_RSTRIDE)           // 5120
#define BT_RSTRIDE 272                     // bytes per B k-row (128h + 8 pad)
#define BT_BYTES (32 * BT_RSTRIDE)         // 8704
#define BN_BYTES (128 * A_RSTRIDE)         // 10240 (non-trans B)
#define STAGE_BYTES (A_BYTES + BN_BYTES)   // 15360 (covers both layouts)
#define NSTAGE 3
#define SMEM_MAIN (NSTAGE * STAGE_BYTES)

template <int MODE>
__global__ __launch_bounds__(NTH, 2) void gemm_f16_kernel(
    const float* __restrict__ bias,
    const float* __restrict__ graw,
    const float* __restrict__ hraw,
    float* __restrict__ out)
{
    constexpr bool BTRANS = (MODE != 2);
    extern __shared__ __align__(128) unsigned char dsm[];
    const uint32_t sb = smem_u32(dsm);
    const int tid = threadIdx.x;
    const int wid = tid >> 5, lane = tid & 31;
    const int rowBase = blockIdx.y * 64;
    const int colBase = blockIdx.x * 128;
    const int nchunks = (MODE == 2) ? (HSZ / 32) : ((ISZ + HSZ) / 32);
    const int ldout = (MODE == 2) ? ISZ : HSZ;

    const int wm = (wid >> 2) * 32;   // warp m offset (0 or 32)
    const int wn = (wid & 3) * 32;    // warp n offset

    float acc[2][4][4];
#pragma unroll
    for (int mi = 0; mi < 2; mi++)
#pragma unroll
        for (int ni = 0; ni < 4; ni++)
#pragma unroll
            for (int q = 0; q < 4; q++) acc[mi][ni][q] = 0.0f;

    // ---- chunk loader: A 256 cp16, B 512 cp16 -> 3 per thread ----
    auto load_chunk = [&](int c) {
        const int k0 = c * 32;
        const __half *A, *B;
        int lda, ldb, kk;
        if (MODE == 2) {
            A = g_hn16; lda = HSZ; kk = k0;
            B = g_linw; ldb = HSZ;               // [N,K]
        } else if (k0 < ISZ) {
            A = g_x16; lda = ISZ; kk = k0;
            B = (MODE == 0) ? g_wgx : g_wxh; ldb = HSZ;  // [K,N], ldb = N
        } else {
            A = g_h16; lda = HSZ; kk = k0 - ISZ;
            B = (MODE == 0) ? g_wgh : g_whh; ldb = HSZ;
        }
        const uint32_t base = sb + (c % NSTAGE) * STAGE_BYTES;
        // A: row = tid/4 (0..63), kc = tid%4
        {
            const int row = tid >> 2, kc = tid & 3;
            CP16(base + row * A_RSTRIDE + kc * 16,
                 A + (size_t)(rowBase + row) * lda + kk + kc * 8);
        }
        if (BTRANS) {
            // B [K,N]: 32 k-rows x 256B
#pragma unroll
            for (int j = 0; j < 2; j++) {
                const int idx = tid * 2 + j;
                const int row = idx >> 4, nc = idx & 15;
                CP16(base + A_BYTES + row * BT_RSTRIDE + nc * 16,
                     B + (size_t)(kk + row) * ldb + colBase + nc * 8);
            }
        } else {
            // B [N,K]: 128 n-rows x 64B
#pragma unroll
            for (int j = 0; j < 2; j++) {
                const int idx = tid * 2 + j;
                const int row = idx >> 2, kc = idx & 3;
                CP16(base + A_BYTES + row * A_RSTRIDE + kc * 16,
                     B + (size_t)(colBase + row) * ldb + kk + kc * 8);
            }
        }
        CP_COMMIT();
    };

    load_chunk(0);
    load_chunk(1);

    for (int c = 0; c < nchunks; c++) {
        if (c == nchunks - 1) { CP_WAIT0(); } else { CP_WAIT1(); }
        __syncthreads();
        if (c + 2 < nchunks) load_chunk(c + 2);

        const uint32_t base = sb + (c % NSTAGE) * STAGE_BYTES;
        const uint32_t sA = base;
        const uint32_t sB = base + A_BYTES;

#pragma unroll
        for (int ks = 0; ks < 2; ks++) {
            const int k = ks * 16;
            // A fragments: 2 m-tiles (non-trans, [m][k] rows)
            const uint32_t aoff =
                (uint32_t)(wm + (lane & 15)) * A_RSTRIDE +
                (uint32_t)(k + ((lane >> 4) << 3)) * 2;
            uint32_t af[2][4];
#pragma unroll
            for (int mi = 0; mi < 2; mi++) {
                const uint32_t d = aoff + mi * 16 * A_RSTRIDE;
                LDMATRIX_X4(af[mi][0], af[mi][1], af[mi][2], af[mi][3], sA + d);
            }
            // B fragments: 2 n-pairs
            uint32_t bf[2][4];
            if (BTRANS) {
                const int l8 = lane & 7, t8 = lane >> 3;   // t8: 0..3
#pragma unroll
                for (int np = 0; np < 2; np++) {
                    const uint32_t d =
                        (uint32_t)(k + (t8 & 1) * 8 + l8) * BT_RSTRIDE +
                        (uint32_t)(wn + np * 16 + (t8 >> 1) * 8) * 2;
                    LDMATRIX_X4_T(bf[np][0], bf[np][1], bf[np][2], bf[np][3], sB + d);
                }
            } else {
                const uint32_t boff =
                    (uint32_t)(wn + ((lane >> 4) << 3) + (lane & 7)) * A_RSTRIDE +
                    (uint32_t)(k + (((lane >> 3) & 1) << 3)) * 2;
#pragma unroll
                for (int np = 0; np < 2; np++) {
                    const uint32_t d = boff + np * 16 * A_RSTRIDE;
                    LDMATRIX_X4(bf[np][0], bf[np][1], bf[np][2], bf[np][3], sB + d);
                }
            }
            // 8 MMAs, independent accumulators
#pragma unroll
            for (int mi = 0; mi < 2; mi++)
#pragma unroll
                for (int ni = 0; ni < 4; ni++) {
                    const int np = ni >> 1, q = (ni & 1) * 2;
                    MMA16816(acc[mi][ni], af[mi], bf[np][q], bf[np][q + 1]);
                }
        }
    }

    // ---- epilogue: direct register -> gmem, fused ops ----
#pragma unroll
    for (int mi = 0; mi < 2; mi++) {
#pragma unroll
        for (int ni = 0; ni < 4; ni++) {
            const int col = colBase + wn + ni * 8 + (lane & 3) * 2;
#pragma unroll
            for (int hf = 0; hf < 2; hf++) {
                const int row = rowBase + wm + mi * 16 + (lane >> 2) + hf * 8;
                const float c0 = acc[mi][ni][hf * 2 + 0];
                const float c1 = acc[mi][ni][hf * 2 + 1];
                const size_t oidx = (size_t)row * ldout + col;
                if (MODE == 0) {
                    float2 r;
                    r.x = tanhf(c0 + bias[col]);
                    r.y = tanhf(c1 + bias[col + 1]);
                    *(float2*)&out[oidx] = r;
                } else if (MODE == 1) {
                    const size_t ii = (size_t)row * HSZ + col;
                    const float2 gv = *(const float2*)&graw[ii];
                    const float2 hv = *(const float2*)&hraw[ii];
                    const float t0 = tanhf(c0 + bias[col]);
                    const float t1 = tanhf(c1 + bias[col + 1]);
                    float2 hn;
                    hn.x = gv.x * t0 + (1.0f - gv.x) * hv.x;
                    hn.y = gv.y * t1 + (1.0f - gv.y) * hv.y;
                    *(float2*)&out[oidx] = hn;
                    *(__half2*)&g_hn16[ii] =
                        __halves2half2(__float2half_rn(hn.x), __float2half_rn(hn.y));
                } else {
                    float2 r;
                    r.x = c0 + bias[col];
                    r.y = c1 + bias[col + 1];
                    *(float2*)&out[oidx] = r;
                }
            }
        }
    }
}

// ---------------------------------------------------------------------------
// Launch
// ---------------------------------------------------------------------------
extern "C" void kernel_launch(void* const* d_in, const int* in_sizes, int n_in,
                              void* d_out, int out_size) {
    const float* x     = (const float*)d_in[0];
    const float* h     = (const float*)d_in[1];
    const float* g     = (const float*)d_in[2];
    const float* w_xh  = (const float*)d_in[3];
    const float* w_hh  = (const float*)d_in[4];
    const float* b_h   = (const float*)d_in[5];
    const float* w_gx  = (const float*)d_in[6];
    const float* w_gh  = (const float*)d_in[7];
    const float* b_g   = (const float*)d_in[8];
    const float* lin_w = (const float*)d_in[9];
    const float* lin_b = (const float*)d_in[10];

    float* o     = (float*)d_out;
    float* h_new = o + (size_t)BSZ * ISZ;
    float* g_new = h_new + (size_t)BSZ * HSZ;

    void *x16, *h16, *lw, *gx, *gh, *xh, *hh;
    cudaGetSymbolAddress(&x16, g_x16);
    cudaGetSymbolAddress(&h16, g_h16);
    cudaGetSymbolAddress(&lw, g_linw);
    cudaGetSymbolAddress(&gx, g_wgx);
    cudaGetSymbolAddress(&gh, g_wgh);
    cudaGetSymbolAddress(&xh, g_wxh);
    cudaGetSymbolAddress(&hh, g_whh);

    cudaFuncSetAttribute(gemm_f16_kernel<0>, cudaFuncAttributeMaxDynamicSharedMemorySize, SMEM_MAIN);
    cudaFuncSetAttribute(gemm_f16_kernel<1>, cudaFuncAttributeMaxDynamicSharedMemorySize, SMEM_MAIN);
    cudaFuncSetAttribute(gemm_f16_kernel<2>, cudaFuncAttributeMaxDynamicSharedMemorySize, SMEM_MAIN);

    // fp32 -> fp16 converts (all streaming; no transposes needed)
    conv_kernel<<<(BSZ * ISZ / 4 + 255) / 256, 256>>>((const float4*)x, (__half2*)x16, BSZ * ISZ / 4);
    conv_kernel<<<(BSZ * HSZ / 4 + 255) / 256, 256>>>((const float4*)h, (__half2*)h16, BSZ * HSZ / 4);
    conv_kernel<<<(ISZ * HSZ / 4 + 255) / 256, 256>>>((const float4*)lin_w, (__half2*)lw, ISZ * HSZ / 4);
    conv_kernel<<<(ISZ * HSZ / 4 + 255) / 256, 256>>>((const float4*)w_gx, (__half2*)gx, ISZ * HSZ / 4);
    conv_kernel<<<(HSZ * HSZ / 4 + 255) / 256, 256>>>((const float4*)w_gh, (__half2*)gh, HSZ * HSZ / 4);
    conv_kernel<<<(ISZ * HSZ / 4 + 255) / 256, 256>>>((const float4*)w_xh, (__half2*)xh, ISZ * HSZ / 4);
    conv_kernel<<<(HSZ * HSZ / 4 + 255) / 256, 256>>>((const float4*)w_hh, (__half2*)hh, HSZ * HSZ / 4);

    // GEMMs
    gemm_f16_kernel<0><<<dim3(HSZ / 128, BSZ / 64), NTH, SMEM_MAIN>>>(b_g, nullptr, nullptr, g_new);
    gemm_f16_kernel<1><<<dim3(HSZ / 128, BSZ / 64), NTH, SMEM_MAIN>>>(b_h, g, h, h_new);
    gemm_f16_kernel<2><<<dim3(ISZ / 128, BSZ / 64), NTH, SMEM_MAIN>>>(lin_b, nullptr, nullptr, o);
}

// round 8
// speedup vs baseline: 3.4721x; 1.0356x over previous
#include <cuda_runtime.h>
#include <cuda_fp16.h>
#include <math.h>
#include <cstdint>

#define BSZ 4096
#define ISZ 1024
#define HSZ 2048
#define NTH 256

// ---------------------------------------------------------------------------
// Device scratch: fp16 planes (weights kept in original [K,N] layout)
// ---------------------------------------------------------------------------
__device__ __half g_x16[BSZ * ISZ];
__device__ __half g_h16[BSZ * HSZ];
__device__ __half g_wgx[ISZ * HSZ];   // [K=I, N=H]
__device__ __half g_wgh[HSZ * HSZ];   // [K=H, N=H]
__device__ __half g_wxh[ISZ * HSZ];
__device__ __half g_whh[HSZ * HSZ];
__device__ __half g_linw[ISZ * HSZ];  // [N=I, K=H] (already B-layout)
__device__ __half g_hn16[BSZ * HSZ];

// ---------------------------------------------------------------------------
// PTX helpers (sm_80-era only: must compile for plain sm_103 target)
// ---------------------------------------------------------------------------
__device__ __forceinline__ uint32_t smem_u32(const void* p) {
    uint32_t a;
    asm("{ .reg .u64 t; cvta.to.shared.u64 t, %1; cvt.u32.u64 %0, t; }"
        : "=r"(a) : "l"(p));
    return a;
}

#define CP16(dst, src) \
    asm volatile("cp.async.cg.shared.global [%0], [%1], 16;" :: "r"(dst), "l"(src))
#define CP_COMMIT() asm volatile("cp.async.commit_group;" ::: "memory")
#define CP_WAIT0()  asm volatile("cp.async.wait_group 0;" ::: "memory")
#define CP_WAIT1()  asm volatile("cp.async.wait_group 1;" ::: "memory")

#define LDMATRIX_X4(r0, r1, r2, r3, addr)                                   \
    asm volatile("ldmatrix.sync.aligned.m8n8.x4.shared.b16 {%0,%1,%2,%3}, [%4];" \
                 : "=r"(r0), "=r"(r1), "=r"(r2), "=r"(r3) : "r"(addr))

#define LDMATRIX_X4_T(r0, r1, r2, r3, addr)                                 \
    asm volatile("ldmatrix.sync.aligned.m8n8.x4.trans.shared.b16 {%0,%1,%2,%3}, [%4];" \
                 : "=r"(r0), "=r"(r1), "=r"(r2), "=r"(r3) : "r"(addr))

#define MMA16816(c, a, b0, b1)                                              \
    asm volatile("mma.sync.aligned.m16n8k16.row.col.f32.f16.f16.f32 "       \
                 "{%0,%1,%2,%3}, {%4,%5,%6,%7}, {%8,%9}, {%0,%1,%2,%3};"    \
                 : "+f"((c)[0]), "+f"((c)[1]), "+f"((c)[2]), "+f"((c)[3])   \
                 : "r"((a)[0]), "r"((a)[1]), "r"((a)[2]), "r"((a)[3]),      \
                   "r"(b0), "r"(b1))

// ---------------------------------------------------------------------------
// Prep: single fused fp32 -> fp16 convert over all 7 tensors
// ---------------------------------------------------------------------------
#define NSEG 7
struct ConvSegs {
    const float4* src[NSEG];
    __half2*      dst[NSEG];
    int           n4[NSEG];    // float4 count per segment
};

__global__ void conv_all_kernel(ConvSegs s) {
    int i = blockIdx.x * blockDim.x + threadIdx.x;
#pragma unroll
    for (int t = 0; t < NSEG; t++) {
        if (i < s.n4[t]) {
            float4 v = s.src[t][i];
            s.dst[t][2 * i] =
                __halves2half2(__float2half_rn(v.x), __float2half_rn(v.y));
            s.dst[t][2 * i + 1] =
                __halves2half2(__float2half_rn(v.z), __float2half_rn(v.w));
            return;
        }
        i -= s.n4[t];
    }
}

// ---------------------------------------------------------------------------
// Tiling constants (BM=64, BN=128, BK=32; 8 warps, warp tile 32x32)
// ---------------------------------------------------------------------------
#define A_RSTRIDE 80                       // bytes per A smem row (32h + 8 pad)
#define A_BYTES (64 * A_RSTRIDE)           // 5120
#define BT_RSTRIDE 272                     // bytes per B k-row (128h + 8 pad)
#define BN_BYTES (128 * A_RSTRIDE)         // 10240 (covers BT: 32*272=8704)
#define STAGE_BYTES (A_BYTES + BN_BYTES)   // 15360
#define NSTAGE 3
#define SMEM_MAIN (NSTAGE * STAGE_BYTES)

// ---------------------------------------------------------------------------
// Merged gate GEMM: blockIdx.z = 0 -> g_new, 1 -> h_new. B via ldmatrix.trans.
// ---------------------------------------------------------------------------
__global__ __launch_bounds__(NTH, 2) void gemm_gates_kernel(
    const float* __restrict__ b_g,
    const float* __restrict__ b_h,
    const float* __restrict__ graw,
    const float* __restrict__ hraw,
    float* __restrict__ g_new,
    float* __restrict__ h_new)
{
    extern __shared__ __align__(128) unsigned char dsm[];
    const uint32_t sb = smem_u32(dsm);
    const int tid = threadIdx.x;
    const int wid = tid >> 5, lane = tid & 31;
    const int rowBase = blockIdx.y * 64;
    const int colBase = blockIdx.x * 128;
    const int z = blockIdx.z;
    const int nchunks = (ISZ + HSZ) / 32;   // 96

    const int wm = (wid >> 2) * 32;
    const int wn = (wid & 3) * 32;

    float acc[2][4][4];
#pragma unroll
    for (int mi = 0; mi < 2; mi++)
#pragma unroll
        for (int ni = 0; ni < 4; ni++)
#pragma unroll
            for (int q = 0; q < 4; q++) acc[mi][ni][q] = 0.0f;

    auto load_chunk = [&](int c) {
        const int k0 = c * 32;
        const __half *A, *B;
        int lda, kk;
        if (k0 < ISZ) {
            A = g_x16; lda = ISZ; kk = k0;
            B = z ? g_wxh : g_wgx;
        } else {
            A = g_h16; lda = HSZ; kk = k0 - ISZ;
            B = z ? g_whh : g_wgh;
        }
        const uint32_t base = sb + (c % NSTAGE) * STAGE_BYTES;
        {
            const int row = tid >> 2, kc = tid & 3;
            CP16(base + row * A_RSTRIDE + kc * 16,
                 A + (size_t)(rowBase + row) * lda + kk + kc * 8);
        }
#pragma unroll
        for (int j = 0; j < 2; j++) {
            const int idx = tid * 2 + j;
            const int row = idx >> 4, nc = idx & 15;
            CP16(base + A_BYTES + row * BT_RSTRIDE + nc * 16,
                 B + (size_t)(kk + row) * HSZ + colBase + nc * 8);
        }
        CP_COMMIT();
    };

    load_chunk(0);
    load_chunk(1);

    for (int c = 0; c < nchunks; c++) {
        if (c == nchunks - 1) { CP_WAIT0(); } else { CP_WAIT1(); }
        __syncthreads();
        if (c + 2 < nchunks) load_chunk(c + 2);

        const uint32_t base = sb + (c % NSTAGE) * STAGE_BYTES;
        const uint32_t sA = base;
        const uint32_t sB = base + A_BYTES;

#pragma unroll
        for (int ks = 0; ks < 2; ks++) {
            const int k = ks * 16;
            const uint32_t aoff =
                (uint32_t)(wm + (lane & 15)) * A_RSTRIDE +
                (uint32_t)(k + ((lane >> 4) << 3)) * 2;
            uint32_t af[2][4];
#pragma unroll
            for (int mi = 0; mi < 2; mi++) {
                const uint32_t d = aoff + mi * 16 * A_RSTRIDE;
                LDMATRIX_X4(af[mi][0], af[mi][1], af[mi][2], af[mi][3], sA + d);
            }
            uint32_t bf[2][4];
            const int l8 = lane & 7, t8 = lane >> 3;
#pragma unroll
            for (int np = 0; np < 2; np++) {
                const uint32_t d =
                    (uint32_t)(k + (t8 & 1) * 8 + l8) * BT_RSTRIDE +
                    (uint32_t)(wn + np * 16 + (t8 >> 1) * 8) * 2;
                LDMATRIX_X4_T(bf[np][0], bf[np][1], bf[np][2], bf[np][3], sB + d);
            }
#pragma unroll
            for (int mi = 0; mi < 2; mi++)
#pragma unroll
                for (int ni = 0; ni < 4; ni++) {
                    const int np = ni >> 1, q = (ni & 1) * 2;
                    MMA16816(acc[mi][ni], af[mi], bf[np][q], bf[np][q + 1]);
                }
        }
    }

    const float* bias = z ? b_h : b_g;
    float* out = z ? h_new : g_new;

#pragma unroll
    for (int mi = 0; mi < 2; mi++) {
#pragma unroll
        for (int ni = 0; ni < 4; ni++) {
            const int col = colBase + wn + ni * 8 + (lane & 3) * 2;
#pragma unroll
            for (int hf = 0; hf < 2; hf++) {
                const int row = rowBase + wm + mi * 16 + (lane >> 2) + hf * 8;
                const float c0 = acc[mi][ni][hf * 2 + 0];
                const float c1 = acc[mi][ni][hf * 2 + 1];
                const size_t oidx = (size_t)row * HSZ + col;
                const float t0 = tanhf(c0 + bias[col]);
                const float t1 = tanhf(c1 + bias[col + 1]);
                if (z == 0) {
                    float2 r; r.x = t0; r.y = t1;
                    *(float2*)&out[oidx] = r;
                } else {
                    const float2 gv = *(const float2*)&graw[oidx];
                    const float2 hv = *(const float2*)&hraw[oidx];
                    float2 hn;
                    hn.x = gv.x * t0 + (1.0f - gv.x) * hv.x;
                    hn.y = gv.y * t1 + (1.0f - gv.y) * hv.y;
                    *(float2*)&out[oidx] = hn;
                    *(__half2*)&g_hn16[oidx] =
                        __halves2half2(__float2half_rn(hn.x), __float2half_rn(hn.y));
                }
            }
        }
    }
}

// ---------------------------------------------------------------------------
// Output GEMM: o = h_new @ lin_w^T + lin_b (B is [N,K], non-trans path)
// ---------------------------------------------------------------------------
__global__ __launch_bounds__(NTH, 2) void gemm_out_kernel(
    const float* __restrict__ bias,
    float* __restrict__ out)
{
    extern __shared__ __align__(128) unsigned char dsm[];
    const uint32_t sb = smem_u32(dsm);
    const int tid = threadIdx.x;
    const int wid = tid >> 5, lane = tid & 31;
    const int rowBase = blockIdx.y * 64;
    const int colBase = blockIdx.x * 128;
    const int nchunks = HSZ / 32;   // 64

    const int wm = (wid >> 2) * 32;
    const int wn = (wid & 3) * 32;

    float acc[2][4][4];
#pragma unroll
    for (int mi = 0; mi < 2; mi++)
#pragma unroll
        for (int ni = 0; ni < 4; ni++)
#pragma unroll
            for (int q = 0; q < 4; q++) acc[mi][ni][q] = 0.0f;

    auto load_chunk = [&](int c) {
        const int kk = c * 32;
        const uint32_t base = sb + (c % NSTAGE) * STAGE_BYTES;
        {
            const int row = tid >> 2, kc = tid & 3;
            CP16(base + row * A_RSTRIDE + kc * 16,
                 g_hn16 + (size_t)(rowBase + row) * HSZ + kk + kc * 8);
        }
#pragma unroll
        for (int j = 0; j < 2; j++) {
            const int idx = tid * 2 + j;
            const int row = idx >> 2, kc = idx & 3;
            CP16(base + A_BYTES + row * A_RSTRIDE + kc * 16,
                 g_linw + (size_t)(colBase + row) * HSZ + kk + kc * 8);
        }
        CP_COMMIT();
    };

    load_chunk(0);
    load_chunk(1);

    for (int c = 0; c < nchunks; c++) {
        if (c == nchunks - 1) { CP_WAIT0(); } else { CP_WAIT1(); }
        __syncthreads();
        if (c + 2 < nchunks) load_chunk(c + 2);

        const uint32_t base = sb + (c % NSTAGE) * STAGE_BYTES;
        const uint32_t sA = base;
        const uint32_t sB = base + A_BYTES;

#pragma unroll
        for (int ks = 0; ks < 2; ks++) {
            const int k = ks * 16;
            const uint32_t aoff =
                (uint32_t)(wm + (lane & 15)) * A_RSTRIDE +
                (uint32_t)(k + ((lane >> 4) << 3)) * 2;
            uint32_t af[2][4];
#pragma unroll
            for (int mi = 0; mi < 2; mi++) {
                const uint32_t d = aoff + mi * 16 * A_RSTRIDE;
                LDMATRIX_X4(af[mi][0], af[mi][1], af[mi][2], af[mi][3], sA + d);
            }
            const uint32_t boff =
                (uint32_t)(wn + ((lane >> 4) << 3) + (lane & 7)) * A_RSTRIDE +
                (uint32_t)(k + (((lane >> 3) & 1) << 3)) * 2;
            uint32_t bf[2][4];
#pragma unroll
            for (int np = 0; np < 2; np++) {
                const uint32_t d = boff + np * 16 * A_RSTRIDE;
                LDMATRIX_X4(bf[np][0], bf[np][1], bf[np][2], bf[np][3], sB + d);
            }
#pragma unroll
            for (int mi = 0; mi < 2; mi++)
#pragma unroll
                for (int ni = 0; ni < 4; ni++) {
                    const int np = ni >> 1, q = (ni & 1) * 2;
                    MMA16816(acc[mi][ni], af[mi], bf[np][q], bf[np][q + 1]);
                }
        }
    }

#pragma unroll
    for (int mi = 0; mi < 2; mi++) {
#pragma unroll
        for (int ni = 0; ni < 4; ni++) {
            const int col = colBase + wn + ni * 8 + (lane & 3) * 2;
#pragma unroll
            for (int hf = 0; hf < 2; hf++) {
                const int row = rowBase + wm + mi * 16 + (lane >> 2) + hf * 8;
                float2 r;
                r.x = acc[mi][ni][hf * 2 + 0] + bias[col];
                r.y = acc[mi][ni][hf * 2 + 1] + bias[col + 1];
                *(float2*)&out[(size_t)row * ISZ + col] = r;
            }
        }
    }
}

// ---------------------------------------------------------------------------
// Launch
// ---------------------------------------------------------------------------
extern "C" void kernel_launch(void* const* d_in, const int* in_sizes, int n_in,
                              void* d_out, int out_size) {
    const float* x     = (const float*)d_in[0];
    const float* h     = (const float*)d_in[1];
    const float* g     = (const float*)d_in[2];
    const float* w_xh  = (const float*)d_in[3];
    const float* w_hh  = (const float*)d_in[4];
    const float* b_h   = (const float*)d_in[5];
    const float* w_gx  = (const float*)d_in[6];
    const float* w_gh  = (const float*)d_in[7];
    const float* b_g   = (const float*)d_in[8];
    const float* lin_w = (const float*)d_in[9];
    const float* lin_b = (const float*)d_in[10];

    float* o     = (float*)d_out;
    float* h_new = o + (size_t)BSZ * ISZ;
    float* g_new = h_new + (size_t)BSZ * HSZ;

    void *x16, *h16, *lw, *gx, *gh, *xh, *hh;
    cudaGetSymbolAddress(&x16, g_x16);
    cudaGetSymbolAddress(&h16, g_h16);
    cudaGetSymbolAddress(&lw, g_linw);
    cudaGetSymbolAddress(&gx, g_wgx);
    cudaGetSymbolAddress(&gh, g_wgh);
    cudaGetSymbolAddress(&xh, g_wxh);
    cudaGetSymbolAddress(&hh, g_whh);

    cudaFuncSetAttribute(gemm_gates_kernel, cudaFuncAttributeMaxDynamicSharedMemorySize, SMEM_MAIN);
    cudaFuncSetAttribute(gemm_out_kernel,   cudaFuncAttributeMaxDynamicSharedMemorySize, SMEM_MAIN);

    // single fused fp32 -> fp16 convert
    ConvSegs segs;
    segs.src[0] = (const float4*)x;     segs.dst[0] = (__half2*)x16; segs.n4[0] = BSZ * ISZ / 4;
    segs.src[1] = (const float4*)h;     segs.dst[1] = (__half2*)h16; segs.n4[1] = BSZ * HSZ / 4;
    segs.src[2] = (const float4*)lin_w; segs.dst[2] = (__half2*)lw;  segs.n4[2] = ISZ * HSZ / 4;
    segs.src[3] = (const float4*)w_gx;  segs.dst[3] = (__half2*)gx;  segs.n4[3] = ISZ * HSZ / 4;
    segs.src[4] = (const float4*)w_gh;  segs.dst[4] = (__half2*)gh;  segs.n4[4] = HSZ * HSZ / 4;
    segs.src[5] = (const float4*)w_xh;  segs.dst[5] = (__half2*)xh;  segs.n4[5] = ISZ * HSZ / 4;
    segs.src[6] = (const float4*)w_hh;  segs.dst[6] = (__half2*)hh;  segs.n4[6] = HSZ * HSZ / 4;
    int total4 = 0;
    for (int t = 0; t < NSEG; t++) total4 += segs.n4[t];
    conv_all_kernel<<<(total4 + 255) / 256, 256>>>(segs);

    // merged gate GEMMs (z=0: g_new, z=1: h_new)
    gemm_gates_kernel<<<dim3(HSZ / 128, BSZ / 64, 2), NTH, SMEM_MAIN>>>(
        b_g, b_h, g, h, g_new, h_new);

    // output GEMM
    gemm_out_kernel<<<dim3(ISZ / 128, BSZ / 64), NTH, SMEM_MAIN>>>(lin_b, o);
}